// round 17
// baseline (speedup 1.0000x reference)
#include <cuda_runtime.h>
#include <cstdint>

// Problem constants
#define Bq     8
#define NIN    512
#define NOUT   1024
#define Cc     16
#define OUTC   32
#define KW     5

// Tiling
#define MTILE  64                 // m per block
#define MT     (NOUT / MTILE)     // 16
#define GRIDB  (Bq * MT)          // 128 blocks
#define GTHREADS 512              // 16 warps: 4 m-subtiles x 4 k-quarters
#define KQ     4
#define KSTEPS 16                 // (NIN/KQ)/8

#define LOG2E 1.4426950408889634f

// dynamic smem partition (floats):
//   sB   [0 .. 8192)   : r staging, then conv output in fragment layout (32KB)
//   zred [8192 .. 12288): KQ x MTILE x Cc partials (16KB)
// total 49152 bytes (default dynamic limit)
#define SB_OFF   0
#define ZRED_OFF 8192
#define DSMEM_BYTES 49152

__device__ __forceinline__ float ex2a(float x) {
    float r; asm("ex2.approx.f32 %0, %1;" : "=f"(r) : "f"(x)); return r;
}
__device__ __forceinline__ unsigned f2tf32(float x) {
    unsigned r; asm("cvt.rna.tf32.f32 %0, %1;" : "=r"(r) : "f"(x)); return r;
}
__device__ __forceinline__ void ffma2(uint64_t& d, uint64_t a, uint64_t b) {
    asm("fma.rn.f32x2 %0, %1, %2, %0;" : "+l"(d) : "l"(a), "l"(b));
}
__device__ __forceinline__ uint64_t pack2(float lo, float hi) {
    uint64_t r; asm("mov.b64 %0, {%1, %2};" : "=l"(r) : "f"(lo), "f"(hi)); return r;
}
__device__ __forceinline__ void unpack2(uint64_t v, float& lo, float& hi) {
    asm("mov.b64 {%0, %1}, %2;" : "=f"(lo), "=f"(hi) : "l"(v));
}
__device__ __forceinline__ void mma_tf32(float d[4], const unsigned a[4],
                                         unsigned b0, unsigned b1) {
    asm volatile(
        "mma.sync.aligned.m16n8k8.row.col.f32.tf32.tf32.f32 "
        "{%0,%1,%2,%3}, {%4,%5,%6,%7}, {%8,%9}, {%0,%1,%2,%3};"
        : "+f"(d[0]), "+f"(d[1]), "+f"(d[2]), "+f"(d[3])
        : "r"(a[0]), "r"(a[1]), "r"(a[2]), "r"(a[3]), "r"(b0), "r"(b1));
}

// ---------------------------------------------------------------------------
// Single fused kernel — each block is fully self-sufficient:
// conv (redundant per block) -> fragment smem -> exps -> tf32 MMA -> linear.
// grid 128 blocks (b = blk>>4, mt = blk&15), block 512.
// Fragment smem layout (proven R8): a(n,c) = (n>>2)*64 + (c>>3)*32
//                                           + (n&3)*8 + (c&7)
// ---------------------------------------------------------------------------
__global__ void __launch_bounds__(GTHREADS, 1)
fused_kernel(const float* __restrict__ r,
             const float* __restrict__ conv_w,
             const float* __restrict__ conv_b,
             const float* __restrict__ xc,
             const float* __restrict__ xt,
             const float* __restrict__ sigma,
             const float* __restrict__ lw,
             const float* __restrict__ lb,
             float* __restrict__ out) {
    extern __shared__ __align__(16) float dsm[];
    float* sB   = dsm + SB_OFF;     // staging, then conv fragments
    float* zred = dsm + ZRED_OFF;   // partials

    __shared__ __align__(8) float2 swsp[Cc * KW * (Cc / 2)];  // packed weights, 5KB
    __shared__ __align__(16) float shlwT[Cc * OUTC];          // transposed [c][o]
    __shared__ float sh_nh[Cc];
    __shared__ int   sh_alleq;

    const int blk = blockIdx.x;
    const int b   = blk >> 4;
    const int mt  = blk & 15;
    const int t   = threadIdx.x;
    const int l   = t & 31;
    const int w   = t >> 5;

    // ---- setup: stage r[b] into sB (coalesced), pack weights, constants ----
    {
        const float4* rsrc = reinterpret_cast<const float4*>(r + (size_t)b * Cc * NIN);
        float4* stg = reinterpret_cast<float4*>(sB);
        #pragma unroll
        for (int j = 0; j < 4; j++) stg[j * 512 + t] = __ldg(&rsrc[j * 512 + t]);
    }
    // packed weight pairs: swsp[(ci*5+k)*8 + cp] = {w[2cp][ci][k], w[2cp+1][ci][k]}
    // conv_w[c*80 + ci*5 + k] -> for index i: cp = i&7, rest = i>>3 (=ci*5+k)
    for (int i = t; i < 640; i += GTHREADS) {
        int cp = i & 7, rest = i >> 3;
        swsp[rest * 8 + cp] = make_float2(__ldg(conv_w + cp * 160 + rest),
                                          __ldg(conv_w + cp * 160 + 80 + rest));
    }
    if (t < Cc) {
        float sg = sigma[t];
        sh_nh[t] = -0.5f * expf(-2.0f * sg) * LOG2E;
    }
    if (t == 0) {
        float s0 = sigma[0];
        int eq = 1;
        #pragma unroll
        for (int c = 1; c < Cc; c++) eq &= (sigma[c] == s0);
        sh_alleq = eq;
    }
    if (t < Cc * OUTC) {
        int c = t >> 5, o = t & 31;
        shlwT[t] = lw[o * Cc + c];
    }
    __syncthreads();

    // ---- conv: thread (cp = t&7 -> channels 2cp,2cp+1; nblk = t>>3 -> 8 n) ----
    const int cp   = t & 7;
    const int nblk = t >> 3;          // 0..63
    const int n0   = nblk * 8;

    uint64_t acc2[8];
    {
        uint64_t bp = pack2(__ldg(conv_b + 2 * cp), __ldg(conv_b + 2 * cp + 1));
        #pragma unroll
        for (int j = 0; j < 8; j++) acc2[j] = bp;
    }
    #pragma unroll 4
    for (int ci = 0; ci < Cc; ci++) {
        uint64_t rvp[12];
        #pragma unroll
        for (int jj = 0; jj < 12; jj++) {
            int idx = n0 - 2 + jj;
            float v = (idx >= 0 && idx < NIN) ? sB[ci * NIN + idx] : 0.0f;
            rvp[jj] = pack2(v, v);
        }
        #pragma unroll
        for (int k = 0; k < KW; k++) {
            float2 wv = swsp[(ci * KW + k) * 8 + cp];
            uint64_t wp = pack2(wv.x, wv.y);
            #pragma unroll
            for (int j = 0; j < 8; j++) ffma2(acc2[j], rvp[j + k], wp);
        }
    }
    __syncthreads();   // all staged reads complete before overwriting sB

    // store conv results (tf32-rounded) into fragment layout
    {
        const int c0 = 2 * cp;
        #pragma unroll
        for (int j = 0; j < 8; j++) {
            float v0, v1;
            unpack2(acc2[j], v0, v1);
            int n = n0 + j;
            int a = (n >> 2) * 64 + (c0 >> 3) * 32 + (n & 3) * 8 + (c0 & 7);
            *reinterpret_cast<float2*>(&sB[a]) =
                make_float2(__uint_as_float(f2tf32(v0)), __uint_as_float(f2tf32(v1)));
        }
    }

    // ---- exp phase (register-resident, conv-independent) ----
    const int msub = w & 3;
    const int kq   = w >> 2;
    unsigned A[KSTEPS][4];
    const int alleq = sh_alleq;

    if (alleq) {
        const float nh = sh_nh[0];
        const int mrow = mt * MTILE + msub * 16 + (l >> 2);
        const float xm0 = __ldg(xt + (size_t)b * NOUT + mrow);
        const float xm1 = __ldg(xt + (size_t)b * NOUT + mrow + 8);

        const float* xcb = xc + (size_t)b * NIN + kq * 128;
        float xr0 = __ldg(xcb + l);
        float xr1 = __ldg(xcb + 32 + l);
        float xr2 = __ldg(xcb + 64 + l);
        float xr3 = __ldg(xcb + 96 + l);

        #pragma unroll
        for (int ks = 0; ks < KSTEPS; ks++) {
            const float xsrc = (ks < 8) ? ((ks < 4) ? xr0 : xr1)
                                        : ((ks < 12) ? xr2 : xr3);
            const int srca = (ks & 3) * 8 + (l & 3);
            float xna = __shfl_sync(0xffffffffu, xsrc, srca);
            float xnb = __shfl_sync(0xffffffffu, xsrc, srca + 4);
            float d;
            // ex2 bits used directly as tf32 (HW truncates) — no CVT in chain
            d = xm0 - xna; A[ks][0] = __float_as_uint(ex2a(d * d * nh));
            d = xm1 - xna; A[ks][1] = __float_as_uint(ex2a(d * d * nh));
            d = xm0 - xnb; A[ks][2] = __float_as_uint(ex2a(d * d * nh));
            d = xm1 - xnb; A[ks][3] = __float_as_uint(ex2a(d * d * nh));
        }
    }
    __syncthreads();   // conv fragments visible to all warps

    if (alleq) {
        // ---- tf32 MMA: conflict-free LDS.32 fragment reads (proven R8) ----
        float D0[4] = {0.f, 0.f, 0.f, 0.f};
        float D1[4] = {0.f, 0.f, 0.f, 0.f};
        const int lof = (l & 3) * 8 + (l >> 2);

        #pragma unroll
        for (int ks = 0; ks < KSTEPS; ks++) {
            const int kbase = kq * 2048 + ks * 128 + lof;
            unsigned b00 = __float_as_uint(sB[kbase]);
            unsigned b01 = __float_as_uint(sB[kbase + 64]);
            unsigned b10 = __float_as_uint(sB[kbase + 32]);
            unsigned b11 = __float_as_uint(sB[kbase + 96]);
            mma_tf32(D0, A[ks], b00, b01);
            mma_tf32(D1, A[ks], b10, b11);
        }

        const int ml = msub * 16 + (l >> 2);
        const int c0 = (l & 3) * 2;
        float* zq = zred + (size_t)kq * MTILE * Cc;
        *reinterpret_cast<float2*>(&zq[ml * Cc + c0])            = make_float2(D0[0], D0[1]);
        *reinterpret_cast<float2*>(&zq[(ml + 8) * Cc + c0])      = make_float2(D0[2], D0[3]);
        *reinterpret_cast<float2*>(&zq[ml * Cc + c0 + 8])        = make_float2(D1[0], D1[1]);
        *reinterpret_cast<float2*>(&zq[(ml + 8) * Cc + c0 + 8])  = make_float2(D1[2], D1[3]);
    } else {
        // ---- generic per-channel sigma fallback (correct, not fast) ----
        float nhc[8];
        const int chalf = l & 1;
        #pragma unroll
        for (int j = 0; j < 8; j++) nhc[j] = sh_nh[chalf * 8 + j];
        const int mloc = msub * 16 + (l >> 1);
        const float xm = __ldg(xt + (size_t)b * NOUT + mt * MTILE + mloc);
        float acc[8];
        #pragma unroll
        for (int j = 0; j < 8; j++) acc[j] = 0.0f;
        for (int i = 0; i < NIN / KQ; i++) {
            const int n = kq * (NIN / KQ) + i;
            float dx = xm - __ldg(xc + (size_t)b * NIN + n);
            float d  = dx * dx;
            const int base = (n >> 2) * 64 + chalf * 32 + (n & 3) * 8;
            float4 ra = *reinterpret_cast<const float4*>(&sB[base]);
            float4 rb = *reinterpret_cast<const float4*>(&sB[base + 4]);
            acc[0] += ex2a(d * nhc[0]) * ra.x;
            acc[1] += ex2a(d * nhc[1]) * ra.y;
            acc[2] += ex2a(d * nhc[2]) * ra.z;
            acc[3] += ex2a(d * nhc[3]) * ra.w;
            acc[4] += ex2a(d * nhc[4]) * rb.x;
            acc[5] += ex2a(d * nhc[5]) * rb.y;
            acc[6] += ex2a(d * nhc[6]) * rb.z;
            acc[7] += ex2a(d * nhc[7]) * rb.w;
        }
        float* zp = zred + ((size_t)kq * MTILE + mloc) * Cc + chalf * 8;
        *reinterpret_cast<float4*>(zp)     = make_float4(acc[0], acc[1], acc[2], acc[3]);
        *reinterpret_cast<float4*>(zp + 4) = make_float4(acc[4], acc[5], acc[6], acc[7]);
    }
    __syncthreads();

    // fold 4 partial sets into set 0 (256 threads, 1 float4 each)
    {
        float4* rv = reinterpret_cast<float4*>(zred);
        const int NV = MTILE * Cc / 4;   // 256 slots per set
        if (t < NV) {
            float4 s = rv[t];
            #pragma unroll
            for (int q = 1; q < KQ; q++) {
                float4 p = rv[q * NV + t];
                s.x += p.x; s.y += p.y; s.z += p.z; s.w += p.w;
            }
            rv[t] = s;
        }
    }
    __syncthreads();

    // linear C -> OUT_C + bias: thread t -> (ml = t>>3, 4 outputs at og=(t&7)*4)
    {
        const int ml = t >> 3;            // 0..63
        const int og = (t & 7) * 4;       // 0..28
        float z[Cc];
        #pragma unroll
        for (int c = 0; c < Cc; c += 4) {
            float4 zv = *reinterpret_cast<const float4*>(&zred[ml * Cc + c]);
            z[c] = zv.x; z[c + 1] = zv.y; z[c + 2] = zv.z; z[c + 3] = zv.w;
        }
        float4 o4;
        o4.x = __ldg(lb + og + 0); o4.y = __ldg(lb + og + 1);
        o4.z = __ldg(lb + og + 2); o4.w = __ldg(lb + og + 3);
        #pragma unroll
        for (int c = 0; c < Cc; c++) {
            float zc = z[c];
            float4 wv = *reinterpret_cast<const float4*>(&shlwT[c * OUTC + og]);
            o4.x += zc * wv.x; o4.y += zc * wv.y;
            o4.z += zc * wv.z; o4.w += zc * wv.w;
        }
        *reinterpret_cast<float4*>(
            out + (((size_t)b * NOUT) + mt * MTILE + ml) * OUTC + og) = o4;
    }
}

// ---------------------------------------------------------------------------
// Launch. Inputs (metadata order):
// 0 r (8,16,512) | 1 x_context (8,512,1) | 2 y_context (unused) |
// 3 x_target (8,1024,1) | 4 conv_w (16,16,5) | 5 conv_b (16) |
// 6 sigma (16) | 7 lin_w (32,16) | 8 lin_b (32)  -> out (8,1024,32) f32
// Single self-sufficient kernel: no g_rt, no second launch, no barrier.
// ---------------------------------------------------------------------------
extern "C" void kernel_launch(void* const* d_in, const int* in_sizes, int n_in,
                              void* d_out, int out_size) {
    const float* r      = (const float*)d_in[0];
    const float* xc     = (const float*)d_in[1];
    const float* xt     = (const float*)d_in[3];
    const float* conv_w = (const float*)d_in[4];
    const float* conv_b = (const float*)d_in[5];
    const float* sigma  = (const float*)d_in[6];
    const float* lin_w  = (const float*)d_in[7];
    const float* lin_b  = (const float*)d_in[8];
    float* out = (float*)d_out;

    cudaFuncSetAttribute(fused_kernel,
                         cudaFuncAttributeMaxDynamicSharedMemorySize, DSMEM_BYTES);
    fused_kernel<<<GRIDB, GTHREADS, DSMEM_BYTES>>>(
        r, conv_w, conv_b, xc, xt, sigma, lin_w, lin_b, out);
}